// round 3
// baseline (speedup 1.0000x reference)
#include <cuda_runtime.h>

#define NB     512
#define NU_PTS 32
#define NV_PTS 128
#define NC     16

typedef unsigned long long u64;

// ---------- f32x2 packed-math + shared-memory asm helpers ----------
__device__ __forceinline__ unsigned s2u(const void* p) {
    return (unsigned)__cvta_generic_to_shared(p);
}
__device__ __forceinline__ void lds2(unsigned a, u64& x, u64& y) {
    asm volatile("ld.shared.v2.u64 {%0,%1}, [%2];" : "=l"(x), "=l"(y) : "r"(a));
}
__device__ __forceinline__ void sts2(unsigned a, u64 x, u64 y) {
    asm volatile("st.shared.v2.u64 [%0], {%1,%2};" :: "r"(a), "l"(x), "l"(y) : "memory");
}
__device__ __forceinline__ u64 f2fma(u64 a, u64 b, u64 c) {
    u64 d; asm("fma.rn.f32x2 %0, %1, %2, %3;" : "=l"(d) : "l"(a), "l"(b), "l"(c)); return d;
}
__device__ __forceinline__ u64 f2mul(u64 a, u64 b) {
    u64 d; asm("mul.rn.f32x2 %0, %1, %2;" : "=l"(d) : "l"(a), "l"(b)); return d;
}
__device__ __forceinline__ u64 fpack(float a, float b) {
    u64 d; asm("mov.b64 %0, {%1,%2};" : "=l"(d) : "f"(a), "f"(b)); return d;
}
__device__ __forceinline__ void funpack(u64 p, float& a, float& b) {
    asm("mov.b64 {%0,%1}, %2;" : "=f"(a), "=f"(b) : "l"(p));
}
__device__ __forceinline__ void stg64(float* p, u64 v) {
    asm volatile("st.global.b64 [%0], %1;" :: "l"(p), "l"(v) : "memory");
}

// column swizzle: permutation of 0..127, gives conflict-free 16B shared access
// for both consecutive-v (stage1 STS) and stride-2-v (stage2 LDS) lane patterns
__device__ __forceinline__ int swz(int v) { return v ^ (v >> 3); }

__global__ __launch_bounds__(256, 4)
void surf_eval_kernel(const float4* __restrict__ ctrl,   // [NB][16][16] (x,y,z,w)
                      const float4* __restrict__ Nu4,    // [32]
                      const float4* __restrict__ Nv4,    // [128]
                      const int*    __restrict__ uspan,  // [32]
                      const int*    __restrict__ vspan,  // [128]
                      float*        __restrict__ out)    // [NB][32][128][3]
{
    __shared__ float4 sctrl[NC][NC];          // 4 KB
    __shared__ float4 sT[NC][NV_PTS];         // 32 KB, columns swizzled by swz(v)
    __shared__ float4 sNuP[NU_PTS][2];        // 1 KB  : {(nx,nx,ny,ny),(nz,nz,nw,nw)}
    __shared__ float4 sNvP[NV_PTS][2];        // 4 KB
    __shared__ int    sUs[NU_PTS];
    __shared__ int    sVs[NV_PTS];

    const int tid = threadIdx.x;
    const int b   = blockIdx.x;

    // ---- load ctrl tile + duplicated-pair basis + spans ----
    ((float4*)sctrl)[tid] = ctrl[b * 256 + tid];
    if (tid < NV_PTS) {
        float4 nv = Nv4[tid];
        sNvP[tid][0] = make_float4(nv.x, nv.x, nv.y, nv.y);
        sNvP[tid][1] = make_float4(nv.z, nv.z, nv.w, nv.w);
        sVs[tid] = vspan[tid] - 3;
    } else if (tid < NV_PTS + NU_PTS) {
        int u = tid - NV_PTS;
        float4 nu = Nu4[u];
        sNuP[u][0] = make_float4(nu.x, nu.x, nu.y, nu.y);
        sNuP[u][1] = make_float4(nu.z, nu.z, nu.w, nu.w);
        sUs[u] = uspan[u] - 3;
    }
    __syncthreads();

    const unsigned sctrl_a = s2u(sctrl);
    const unsigned sT_a    = s2u(sT);
    const unsigned sNvP_a  = s2u(sNvP);
    const unsigned sNuP_a  = s2u(sNuP);

    // ---- stage 1: T[ui][v] = sum_j Nv[v,j] * ctrl[ui, vs+j]  (packed f32x2) ----
    #pragma unroll
    for (int it = 0; it < 8; ++it) {
        int idx = it * 256 + tid;
        int ui  = idx >> 7;        // 0..15
        int v   = idx & 127;       // 0..127
        int vs  = sVs[v];

        u64 nA0, nA1, nB0, nB1;    // (nx,nx)(ny,ny)(nz,nz)(nw,nw)
        lds2(sNvP_a + v * 32,      nA0, nA1);
        lds2(sNvP_a + v * 32 + 16, nB0, nB1);

        unsigned ca = sctrl_a + ui * 256 + vs * 16;
        u64 c0xy, c0zw, c1xy, c1zw, c2xy, c2zw, c3xy, c3zw;
        lds2(ca,      c0xy, c0zw);
        lds2(ca + 16, c1xy, c1zw);
        lds2(ca + 32, c2xy, c2zw);
        lds2(ca + 48, c3xy, c3zw);

        u64 txy = f2mul(nA0, c0xy);
        txy = f2fma(nA1, c1xy, txy);
        txy = f2fma(nB0, c2xy, txy);
        txy = f2fma(nB1, c3xy, txy);
        u64 tzw = f2mul(nA0, c0zw);
        tzw = f2fma(nA1, c1zw, tzw);
        tzw = f2fma(nB0, c2zw, tzw);
        tzw = f2fma(nB1, c3zw, tzw);

        sts2(sT_a + ui * 2048 + swz(v) * 16, txy, tzw);
    }
    __syncthreads();

    // ---- stage 2: rotating 4-row register window, v-pair per thread ----
    {
        const int vp = tid & 63;           // v-pair index
        const int v0 = vp * 2;             // even v
        const int uh = tid >> 6;           // 0..3 (warp-uniform)
        const int u0 = uh * 8;
        const unsigned col0 = (unsigned)swz(v0) * 16;
        const unsigned col1 = (unsigned)swz(v0 + 1) * 16;

        int r = sUs[u0];
        // window rows r..r+3 : (xy,zw) for v0 and v0+1
        u64 A0,B0,C0,D0, A1,B1,C1,D1, A2,B2,C2,D2, A3,B3,C3,D3;
        {
            unsigned ra = sT_a + r * 2048;
            lds2(ra + col0,        A0, B0); lds2(ra + col1,        C0, D0);
            lds2(ra + 2048 + col0, A1, B1); lds2(ra + 2048 + col1, C1, D1);
            lds2(ra + 4096 + col0, A2, B2); lds2(ra + 4096 + col1, C2, D2);
            lds2(ra + 6144 + col0, A3, B3); lds2(ra + 6144 + col1, C3, D3);
        }

        float* op = out + (((size_t)b * NU_PTS + u0) * NV_PTS + v0) * 3;

        #pragma unroll
        for (int k = 0; k < 8; ++k) {
            const int u  = u0 + k;
            const int i0 = sUs[u];
            while (r < i0) {               // warp-uniform shift
                A0=A1; B0=B1; C0=C1; D0=D1;
                A1=A2; B1=B2; C1=C2; D1=D2;
                A2=A3; B2=B3; C2=C3; D2=D3;
                ++r;
                unsigned ra = sT_a + (r + 3) * 2048;
                lds2(ra + col0, A3, B3);
                lds2(ra + col1, C3, D3);
            }
            u64 nA0, nA1, nB0, nB1;
            lds2(sNuP_a + u * 32,      nA0, nA1);
            lds2(sNuP_a + u * 32 + 16, nB0, nB1);

            u64 xy0 = f2mul(nA0, A0); xy0 = f2fma(nA1, A1, xy0); xy0 = f2fma(nB0, A2, xy0); xy0 = f2fma(nB1, A3, xy0);
            u64 zw0 = f2mul(nA0, B0); zw0 = f2fma(nA1, B1, zw0); zw0 = f2fma(nB0, B2, zw0); zw0 = f2fma(nB1, B3, zw0);
            u64 xy1 = f2mul(nA0, C0); xy1 = f2fma(nA1, C1, xy1); xy1 = f2fma(nB0, C2, xy1); xy1 = f2fma(nB1, C3, xy1);
            u64 zw1 = f2mul(nA0, D0); zw1 = f2fma(nA1, D1, zw1); zw1 = f2fma(nB0, D2, zw1); zw1 = f2fma(nB1, D3, zw1);

            float z0, w0, z1, w1;
            funpack(zw0, z0, w0);
            funpack(zw1, z1, w1);
            float r0 = __fdividef(1.0f, fmaxf(w0, 1e-8f));
            float r1 = __fdividef(1.0f, fmaxf(w1, 1e-8f));

            u64 xys0 = f2mul(xy0, fpack(r0, r0));
            u64 xys1 = f2mul(xy1, fpack(r1, r1));
            float x1s, y1s;
            funpack(xys1, x1s, y1s);

            stg64(op,     xys0);                    // x0,y0
            stg64(op + 2, fpack(z0 * r0, x1s));     // z0,x1
            stg64(op + 4, fpack(y1s, z1 * r1));     // y1,z1
            op += NV_PTS * 3;                       // next u row
        }
    }
}

extern "C" void kernel_launch(void* const* d_in, const int* in_sizes, int n_in,
                              void* d_out, int out_size)
{
    const float4* ctrl  = (const float4*)d_in[0];
    const float4* Nu4   = (const float4*)d_in[1];
    const float4* Nv4   = (const float4*)d_in[2];
    const int*    uspan = (const int*)d_in[3];
    const int*    vspan = (const int*)d_in[4];
    float*        out   = (float*)d_out;

    surf_eval_kernel<<<NB, 256>>>(ctrl, Nu4, Nv4, uspan, vspan, out);
}

// round 4
// speedup vs baseline: 1.4089x; 1.4089x over previous
#include <cuda_runtime.h>

#define NB     512
#define NU_PTS 32
#define NV_PTS 128
#define NVH    64          // v points per block (half)
#define NC     16

__global__ __launch_bounds__(256, 5)
void surf_eval_kernel(const float4* __restrict__ ctrl,   // [NB][16][16] of (x,y,z,w)
                      const float4* __restrict__ Nu4,    // [32]
                      const float4* __restrict__ Nv4,    // [128]
                      const int*    __restrict__ uspan,  // [32]
                      const int*    __restrict__ vspan,  // [128]
                      float*        __restrict__ out)    // [NB][32][128][3]
{
    __shared__ float4 sctrl[NC][NC];        // 4 KB
    __shared__ float4 sT[NC][NVH];          // 16 KB : T[ui][vl] for this v-half
    __shared__ float4 sNu[NU_PTS];          // 512 B
    __shared__ float4 sNv[NVH];             // 1 KB
    __shared__ int    sUs[NU_PTS];
    __shared__ int    sVs[NVH];

    const int tid = threadIdx.x;
    const int b   = blockIdx.x >> 1;        // batch
    const int vh  = blockIdx.x & 1;         // v-half: v = vh*64 + vl
    const int vbase = vh * NVH;

    // ---- load: ctrl tile (256 float4, one per thread), basis + spans ----
    ((float4*)sctrl)[tid] = ctrl[b * 256 + tid];
    if (tid < NVH) {
        sNv[tid] = Nv4[vbase + tid];
        sVs[tid] = vspan[vbase + tid] - 3;
    } else if (tid < NVH + NU_PTS) {
        int u = tid - NVH;
        sNu[u] = Nu4[u];
        sUs[u] = uspan[u] - 3;
    }
    __syncthreads();

    // ---- stage 1: contract over vj (4 sparse terms) ----
    // 16 ui rows x 64 vl = 1024 outputs, 256 threads -> 4 iterations
    #pragma unroll
    for (int it = 0; it < 4; ++it) {
        int idx = it * 256 + tid;
        int ui  = idx >> 6;        // 0..15
        int vl  = idx & 63;        // 0..63
        int vs  = sVs[vl];
        float4 nv = sNv[vl];
        float4 c0 = sctrl[ui][vs + 0];
        float4 c1 = sctrl[ui][vs + 1];
        float4 c2 = sctrl[ui][vs + 2];
        float4 c3 = sctrl[ui][vs + 3];
        float4 t;
        t.x = nv.x * c0.x + nv.y * c1.x + nv.z * c2.x + nv.w * c3.x;
        t.y = nv.x * c0.y + nv.y * c1.y + nv.z * c2.y + nv.w * c3.y;
        t.z = nv.x * c0.z + nv.y * c1.z + nv.z * c2.z + nv.w * c3.z;
        t.w = nv.x * c0.w + nv.y * c1.w + nv.z * c2.w + nv.w * c3.w;
        sT[ui][vl] = t;
    }
    __syncthreads();

    // ---- stage 2: rotating register window over sT rows ----
    // thread -> (vl = tid&63, u-quarter = tid>>6 : u in [q*8, q*8+8) )
    // uspan is monotone in u and tid>>6 is warp-uniform, so the window-shift
    // loop is non-divergent and each sT row is loaded exactly once per thread.
    {
        const int vl = tid & 63;
        const int uq = tid >> 6;              // 0..3, uniform within a warp
        const int u0 = uq * 8;

        int r = sUs[u0];                      // current window base row
        float4 t0 = sT[r + 0][vl];
        float4 t1 = sT[r + 1][vl];
        float4 t2 = sT[r + 2][vl];
        float4 t3 = sT[r + 3][vl];

        float* op = out + (((size_t)b * NU_PTS + u0) * NV_PTS + vbase + vl) * 3;

        #pragma unroll
        for (int k = 0; k < 8; ++k) {
            const int u  = u0 + k;
            const int i0 = sUs[u];
            while (r < i0) {                  // warp-uniform shift (0 or 1 typical)
                t0 = t1; t1 = t2; t2 = t3;
                t3 = sT[r + 4][vl];
                ++r;
            }
            float4 nu = sNu[u];
            float x = nu.x * t0.x + nu.y * t1.x + nu.z * t2.x + nu.w * t3.x;
            float y = nu.x * t0.y + nu.y * t1.y + nu.z * t2.y + nu.w * t3.y;
            float z = nu.x * t0.z + nu.y * t1.z + nu.z * t2.z + nu.w * t3.z;
            float w = nu.x * t0.w + nu.y * t1.w + nu.z * t2.w + nu.w * t3.w;

            float rcp = __fdividef(1.0f, fmaxf(w, 1e-8f));
            op[0] = x * rcp;
            op[1] = y * rcp;
            op[2] = z * rcp;
            op += NV_PTS * 3;                 // next u row
        }
    }
}

extern "C" void kernel_launch(void* const* d_in, const int* in_sizes, int n_in,
                              void* d_out, int out_size)
{
    const float4* ctrl  = (const float4*)d_in[0];
    const float4* Nu4   = (const float4*)d_in[1];
    const float4* Nv4   = (const float4*)d_in[2];
    const int*    uspan = (const int*)d_in[3];
    const int*    vspan = (const int*)d_in[4];
    float*        out   = (float*)d_out;

    surf_eval_kernel<<<NB * 2, 256>>>(ctrl, Nu4, Nv4, uspan, vspan, out);
}